// round 1
// baseline (speedup 1.0000x reference)
#include <cuda_runtime.h>
#include <cstdint>
#include <math.h>

// Problem constants
#define B_  32
#define T_  1536
#define C_  768
#define G_  2
#define VG_ 160
#define M_TOTAL (B_*T_)       // 49152
#define N1 (G_*VG_)           // 320
#define K1 C_                 // 768
#define N2 C_                 // 768
#define K2 (G_*VG_)           // 320
#define TEMP_ 2.0f

// 63MB scratch for logits (allocation-free rule: __device__ global)
__device__ float g_logits[(size_t)M_TOTAL * N1];

// ---------------- GEMM: C = A(MxK) @ B(KxN) (+bias), 3xTF32 ----------------
#define BM 128
#define BN 64
#define BK 32
#define PITCH_A 36   // BK+4: conflict-free frag reads (bank = 4m+k)
#define PITCH_B 72   // BN+8: conflict-free frag reads (bank = 8k+n)

__device__ __forceinline__ uint32_t f2tf32(float a) {
    uint32_t u;
    asm("cvt.rna.tf32.f32 %0, %1;" : "=r"(u) : "f"(a));
    return u;
}

__device__ __forceinline__ void mma_m16n8k8(float c[4],
    uint32_t a0, uint32_t a1, uint32_t a2, uint32_t a3,
    uint32_t b0, uint32_t b1)
{
    asm volatile(
        "mma.sync.aligned.m16n8k8.row.col.f32.tf32.tf32.f32 "
        "{%0,%1,%2,%3}, {%4,%5,%6,%7}, {%8,%9}, {%0,%1,%2,%3};"
        : "+f"(c[0]), "+f"(c[1]), "+f"(c[2]), "+f"(c[3])
        : "r"(a0), "r"(a1), "r"(a2), "r"(a3), "r"(b0), "r"(b1));
}

template<bool HAS_BIAS>
__global__ __launch_bounds__(256, 2)
void gemm_3xtf32(const float* __restrict__ A, const float* __restrict__ Bg,
                 const float* __restrict__ bias, float* __restrict__ Cg,
                 int Kdim, int Ndim)
{
    __shared__ float As[BM][PITCH_A];   // [m][k]
    __shared__ float Bs[BK][PITCH_B];   // [k][n]

    const int tid  = threadIdx.x;
    const int warp = tid >> 5, lane = tid & 31;
    const int wm = warp >> 1, wn = warp & 1;        // 4x2 warps -> 32x32 warp tile
    const int m0 = blockIdx.y * BM, n0 = blockIdx.x * BN;
    const int gid = lane >> 2, tig = lane & 3;

    float acc[2][4][4];
    #pragma unroll
    for (int mt = 0; mt < 2; mt++)
        #pragma unroll
        for (int nt = 0; nt < 4; nt++)
            #pragma unroll
            for (int r = 0; r < 4; r++) acc[mt][nt][r] = 0.0f;

    for (int k0 = 0; k0 < Kdim; k0 += BK) {
        // Load A tile (128x32 floats, 1024 float4, 4 per thread)
        #pragma unroll
        for (int i = 0; i < 4; i++) {
            int lin = tid + i * 256;
            int r = lin >> 3, c4 = lin & 7;
            float4 v = *(const float4*)(A + (size_t)(m0 + r) * Kdim + k0 + c4 * 4);
            *(float4*)(&As[r][c4 * 4]) = v;
        }
        // Load B tile (32x64 floats, 512 float4, 2 per thread)
        #pragma unroll
        for (int i = 0; i < 2; i++) {
            int lin = tid + i * 256;
            int kr = lin >> 4, n4 = lin & 15;
            float4 v = *(const float4*)(Bg + (size_t)(k0 + kr) * Ndim + n0 + n4 * 4);
            *(float4*)(&Bs[kr][n4 * 4]) = v;
        }
        __syncthreads();

        #pragma unroll
        for (int ks = 0; ks < BK; ks += 8) {
            // A fragments (hi/lo split on the fly)
            uint32_t ah[2][4], al[2][4];
            #pragma unroll
            for (int mt = 0; mt < 2; mt++) {
                int mb = wm * 32 + mt * 16;
                float x0 = As[mb + gid    ][ks + tig    ];
                float x1 = As[mb + gid + 8][ks + tig    ];
                float x2 = As[mb + gid    ][ks + tig + 4];
                float x3 = As[mb + gid + 8][ks + tig + 4];
                ah[mt][0] = f2tf32(x0); al[mt][0] = f2tf32(x0 - __uint_as_float(ah[mt][0]));
                ah[mt][1] = f2tf32(x1); al[mt][1] = f2tf32(x1 - __uint_as_float(ah[mt][1]));
                ah[mt][2] = f2tf32(x2); al[mt][2] = f2tf32(x2 - __uint_as_float(ah[mt][2]));
                ah[mt][3] = f2tf32(x3); al[mt][3] = f2tf32(x3 - __uint_as_float(ah[mt][3]));
            }
            #pragma unroll
            for (int nt = 0; nt < 4; nt++) {
                int nb = wn * 32 + nt * 8 + gid;
                float y0 = Bs[ks + tig    ][nb];
                float y1 = Bs[ks + tig + 4][nb];
                uint32_t bh0 = f2tf32(y0), bl0 = f2tf32(y0 - __uint_as_float(bh0));
                uint32_t bh1 = f2tf32(y1), bl1 = f2tf32(y1 - __uint_as_float(bh1));
                #pragma unroll
                for (int mt = 0; mt < 2; mt++) {
                    mma_m16n8k8(acc[mt][nt], ah[mt][0], ah[mt][1], ah[mt][2], ah[mt][3], bh0, bh1);
                    mma_m16n8k8(acc[mt][nt], ah[mt][0], ah[mt][1], ah[mt][2], ah[mt][3], bl0, bl1);
                    mma_m16n8k8(acc[mt][nt], al[mt][0], al[mt][1], al[mt][2], al[mt][3], bh0, bh1);
                }
            }
        }
        __syncthreads();
    }

    // Epilogue
    #pragma unroll
    for (int mt = 0; mt < 2; mt++) {
        #pragma unroll
        for (int nt = 0; nt < 4; nt++) {
            int row0 = m0 + wm * 32 + mt * 16 + gid;
            int col0 = n0 + wn * 32 + nt * 8 + tig * 2;
            float bv0 = 0.0f, bv1 = 0.0f;
            if (HAS_BIAS) { bv0 = bias[col0]; bv1 = bias[col0 + 1]; }
            Cg[(size_t)(row0    ) * Ndim + col0    ] = acc[mt][nt][0] + bv0;
            Cg[(size_t)(row0    ) * Ndim + col0 + 1] = acc[mt][nt][1] + bv1;
            Cg[(size_t)(row0 + 8) * Ndim + col0    ] = acc[mt][nt][2] + bv0;
            Cg[(size_t)(row0 + 8) * Ndim + col0 + 1] = acc[mt][nt][3] + bv1;
        }
    }
}

// ---------------- Softmax + argmax: one warp per (bt, g) row of 160 ----------------
__global__ void softmax_argmax_kernel(const float* __restrict__ gumbel,
                                      float* __restrict__ probs_out,
                                      float* __restrict__ codes_out)
{
    const int task = blockIdx.x * 8 + (threadIdx.x >> 5);   // 98304 tasks
    const int lane = threadIdx.x & 31;
    const int row = task >> 1, g = task & 1;

    const float* lp = g_logits + (size_t)row * N1 + g * VG_;
    const float* gp = gumbel   + (size_t)row * N1 + g * VG_;

    float z[5];
    float best = -INFINITY;
    int bidx = 0;
    #pragma unroll
    for (int j = 0; j < 5; j++) {
        int v = lane + j * 32;
        z[j] = lp[v] + gp[v];
        if (z[j] > best) { best = z[j]; bidx = v; }   // ascending v keeps first max
    }
    // warp argmax reduction, first-occurrence tie-break
    #pragma unroll
    for (int o = 16; o > 0; o >>= 1) {
        float ov = __shfl_xor_sync(0xffffffffu, best, o);
        int   oi = __shfl_xor_sync(0xffffffffu, bidx, o);
        if (ov > best || (ov == best && oi < bidx)) { best = ov; bidx = oi; }
    }

    const float inv_t = 1.0f / TEMP_;
    float e[5];
    float s = 0.0f;
    #pragma unroll
    for (int j = 0; j < 5; j++) { e[j] = expf((z[j] - best) * inv_t); s += e[j]; }
    #pragma unroll
    for (int o = 16; o > 0; o >>= 1) s += __shfl_xor_sync(0xffffffffu, s, o);
    float inv_s = 1.0f / s;

    float* po = probs_out + (size_t)row * N1 + g * VG_;
    #pragma unroll
    for (int j = 0; j < 5; j++) po[lane + j * 32] = e[j] * inv_s;

    if (lane == 0) codes_out[task] = (float)bidx;
}

// ---------------- launch ----------------
extern "C" void kernel_launch(void* const* d_in, const int* in_sizes, int n_in,
                              void* d_out, int out_size)
{
    const float* x      = (const float*)d_in[0];  // (B,T,C)
    const float* gumbel = (const float*)d_in[1];  // (B,T,G,Vg)
    const float* W      = (const float*)d_in[2];  // (C, G*Vg)
    const float* bias   = (const float*)d_in[3];  // (G*Vg,)
    const float* cb     = (const float*)d_in[4];  // (G,Vg,C) -> (320,768)

    float* out   = (float*)d_out;
    float* quant = out;                                      // M*C
    float* codes = out + (size_t)M_TOTAL * C_;               // M*G
    float* probs = codes + (size_t)M_TOTAL * G_;             // M*N1

    float* logits_ptr = nullptr;
    cudaGetSymbolAddress((void**)&logits_ptr, g_logits);

    // GEMM1: logits = x @ W + b   (M x 768) @ (768 x 320)
    {
        dim3 grid(N1 / BN, M_TOTAL / BM);   // (5, 384)
        gemm_3xtf32<true><<<grid, 256>>>(x, W, bias, logits_ptr, K1, N1);
    }
    // Softmax + argmax + probs
    {
        softmax_argmax_kernel<<<(M_TOTAL * G_) / 8, 256>>>(gumbel, probs, codes);
    }
    // GEMM2: quantized = probs @ codebook   (M x 320) @ (320 x 768)
    {
        dim3 grid(N2 / BN, M_TOTAL / BM);   // (12, 384)
        gemm_3xtf32<false><<<grid, 256>>>(probs, cb, nullptr, quant, K2, N2);
    }
}

// round 5
// speedup vs baseline: 1.6208x; 1.6208x over previous
#include <cuda_runtime.h>
#include <cstdint>
#include <math.h>

// Problem constants
#define B_  32
#define T_  1536
#define C_  768
#define G_  2
#define VG_ 160
#define M_TOTAL (B_*T_)       // 49152
#define N1 (G_*VG_)           // 320
#define K1 C_                 // 768
#define N2 C_                 // 768
#define K2 (G_*VG_)           // 320
#define TEMP_ 2.0f

// 63MB scratch for logits (allocation-free rule: __device__ global)
__device__ float g_logits[(size_t)M_TOTAL * N1];

// ---------------- GEMM: C = A(MxK) @ B(KxN) (+bias), single-pass TF32 ----------------
#define BM 128
#define BN 64
#define BK 32
#define PITCH_A 36   // BK+4
#define PITCH_B 72   // BN+8

__device__ __forceinline__ uint32_t f2tf32(float a) {
    uint32_t u;
    asm("cvt.rna.tf32.f32 %0, %1;" : "=r"(u) : "f"(a));
    return u;
}

__device__ __forceinline__ void mma_m16n8k8(float c[4],
    uint32_t a0, uint32_t a1, uint32_t a2, uint32_t a3,
    uint32_t b0, uint32_t b1)
{
    asm volatile(
        "mma.sync.aligned.m16n8k8.row.col.f32.tf32.tf32.f32 "
        "{%0,%1,%2,%3}, {%4,%5,%6,%7}, {%8,%9}, {%0,%1,%2,%3};"
        : "+f"(c[0]), "+f"(c[1]), "+f"(c[2]), "+f"(c[3])
        : "r"(a0), "r"(a1), "r"(a2), "r"(a3), "r"(b0), "r"(b1));
}

template<bool HAS_BIAS>
__global__ __launch_bounds__(256, 2)
void gemm_tf32(const float* __restrict__ A, const float* __restrict__ Bg,
               const float* __restrict__ bias, float* __restrict__ Cg,
               int Kdim, int Ndim)
{
    __shared__ float As[BM][PITCH_A];   // [m][k]
    __shared__ float Bs[BK][PITCH_B];   // [k][n]

    const int tid  = threadIdx.x;
    const int warp = tid >> 5, lane = tid & 31;
    const int wm = warp >> 1, wn = warp & 1;        // 4x2 warps -> 32x32 warp tile
    const int m0 = blockIdx.y * BM, n0 = blockIdx.x * BN;
    const int gid = lane >> 2, tig = lane & 3;

    float acc[2][4][4];
    #pragma unroll
    for (int mt = 0; mt < 2; mt++)
        #pragma unroll
        for (int nt = 0; nt < 4; nt++)
            #pragma unroll
            for (int r = 0; r < 4; r++) acc[mt][nt][r] = 0.0f;

    for (int k0 = 0; k0 < Kdim; k0 += BK) {
        // Load A tile (128x32 floats, 1024 float4, 4 per thread)
        #pragma unroll
        for (int i = 0; i < 4; i++) {
            int lin = tid + i * 256;
            int r = lin >> 3, c4 = lin & 7;
            float4 v = *(const float4*)(A + (size_t)(m0 + r) * Kdim + k0 + c4 * 4);
            *(float4*)(&As[r][c4 * 4]) = v;
        }
        // Load B tile (32x64 floats, 512 float4, 2 per thread)
        #pragma unroll
        for (int i = 0; i < 2; i++) {
            int lin = tid + i * 256;
            int kr = lin >> 4, n4 = lin & 15;
            float4 v = *(const float4*)(Bg + (size_t)(k0 + kr) * Ndim + n0 + n4 * 4);
            *(float4*)(&Bs[kr][n4 * 4]) = v;
        }
        __syncthreads();

        #pragma unroll
        for (int ks = 0; ks < BK; ks += 8) {
            uint32_t af[2][4];
            #pragma unroll
            for (int mt = 0; mt < 2; mt++) {
                int mb = wm * 32 + mt * 16;
                af[mt][0] = f2tf32(As[mb + gid    ][ks + tig    ]);
                af[mt][1] = f2tf32(As[mb + gid + 8][ks + tig    ]);
                af[mt][2] = f2tf32(As[mb + gid    ][ks + tig + 4]);
                af[mt][3] = f2tf32(As[mb + gid + 8][ks + tig + 4]);
            }
            #pragma unroll
            for (int nt = 0; nt < 4; nt++) {
                int nb = wn * 32 + nt * 8 + gid;
                uint32_t b0 = f2tf32(Bs[ks + tig    ][nb]);
                uint32_t b1 = f2tf32(Bs[ks + tig + 4][nb]);
                #pragma unroll
                for (int mt = 0; mt < 2; mt++)
                    mma_m16n8k8(acc[mt][nt], af[mt][0], af[mt][1], af[mt][2], af[mt][3], b0, b1);
            }
        }
        __syncthreads();
    }

    // Epilogue
    #pragma unroll
    for (int mt = 0; mt < 2; mt++) {
        #pragma unroll
        for (int nt = 0; nt < 4; nt++) {
            int row0 = m0 + wm * 32 + mt * 16 + gid;
            int col0 = n0 + wn * 32 + nt * 8 + tig * 2;
            float bv0 = 0.0f, bv1 = 0.0f;
            if (HAS_BIAS) { bv0 = bias[col0]; bv1 = bias[col0 + 1]; }
            Cg[(size_t)(row0    ) * Ndim + col0    ] = acc[mt][nt][0] + bv0;
            Cg[(size_t)(row0    ) * Ndim + col0 + 1] = acc[mt][nt][1] + bv1;
            Cg[(size_t)(row0 + 8) * Ndim + col0    ] = acc[mt][nt][2] + bv0;
            Cg[(size_t)(row0 + 8) * Ndim + col0 + 1] = acc[mt][nt][3] + bv1;
        }
    }
}

// -------- Softmax + argmax (+ exact rescue for narrow top-2 gaps) --------
// One warp per (bt, g) row of 160.
#define GAP_THRESH  0.01f   // trigger rescue if top1-top2 below this
#define CAND_WINDOW 0.02f   // candidates within this of approx top1

__global__ void softmax_argmax_kernel(const float* __restrict__ gumbel,
                                      const float* __restrict__ x,
                                      const float* __restrict__ W,
                                      const float* __restrict__ bias,
                                      float* __restrict__ probs_out,
                                      float* __restrict__ codes_out)
{
    const int task = blockIdx.x * 8 + (threadIdx.x >> 5);   // 98304 tasks
    const int lane = threadIdx.x & 31;
    const int row = task >> 1, g = task & 1;

    const float* lp = g_logits + (size_t)row * N1 + g * VG_;
    const float* gp = gumbel   + (size_t)row * N1 + g * VG_;

    float z[5];
    float best = -INFINITY, second = -INFINITY;
    int bidx = 0;
    #pragma unroll
    for (int j = 0; j < 5; j++) {
        int v = lane + j * 32;
        z[j] = lp[v] + gp[v];
        if (z[j] > best) { second = best; best = z[j]; bidx = v; }
        else if (z[j] > second) { second = z[j]; }
    }
    // warp (best, second, bidx) pair-merge reduction, first-occurrence tie-break
    #pragma unroll
    for (int o = 16; o > 0; o >>= 1) {
        float ov = __shfl_xor_sync(0xffffffffu, best,   o);
        float os = __shfl_xor_sync(0xffffffffu, second, o);
        int   oi = __shfl_xor_sync(0xffffffffu, bidx,   o);
        if (ov > best || (ov == best && oi < bidx)) {
            second = fmaxf(best, os);
            best = ov; bidx = oi;
        } else {
            second = fmaxf(second, ov);
        }
    }

    // Rescue: exact (fp64) recompute of near-top candidates to pin the argmax.
    if (best - second < GAP_THRESH) {
        double nbest = -1e300;
        int nidx = 0;
        #pragma unroll
        for (int j = 0; j < 5; j++) {
            unsigned m = __ballot_sync(0xffffffffu, z[j] > best - CAND_WINDOW);
            while (m) {
                int l = __ffs(m) - 1; m &= m - 1;
                int v = l + j * 32;
                int col = g * VG_ + v;
                double part = 0.0;
                const float* xr = x + (size_t)row * C_;
                for (int k = lane; k < C_; k += 32)
                    part += (double)xr[k] * (double)W[(size_t)k * N1 + col];
                #pragma unroll
                for (int o = 16; o > 0; o >>= 1)
                    part += __shfl_xor_sync(0xffffffffu, part, o);
                double ze = part + (double)bias[col] + (double)gp[v];
                if (ze > nbest) { nbest = ze; nidx = v; }  // v strictly ascending -> first max kept
            }
        }
        bidx = nidx;
    }

    const float inv_t = 1.0f / TEMP_;
    float e[5];
    float s = 0.0f;
    #pragma unroll
    for (int j = 0; j < 5; j++) { e[j] = __expf((z[j] - best) * inv_t); s += e[j]; }
    #pragma unroll
    for (int o = 16; o > 0; o >>= 1) s += __shfl_xor_sync(0xffffffffu, s, o);
    float inv_s = 1.0f / s;

    float* po = probs_out + (size_t)row * N1 + g * VG_;
    #pragma unroll
    for (int j = 0; j < 5; j++) po[lane + j * 32] = e[j] * inv_s;

    if (lane == 0) codes_out[task] = (float)bidx;
}

// ---------------- launch ----------------
extern "C" void kernel_launch(void* const* d_in, const int* in_sizes, int n_in,
                              void* d_out, int out_size)
{
    const float* x      = (const float*)d_in[0];  // (B,T,C)
    const float* gumbel = (const float*)d_in[1];  // (B,T,G,Vg)
    const float* W      = (const float*)d_in[2];  // (C, G*Vg)
    const float* bias   = (const float*)d_in[3];  // (G*Vg,)
    const float* cb     = (const float*)d_in[4];  // (G,Vg,C) -> (320,768)

    float* out   = (float*)d_out;
    float* quant = out;                                      // M*C
    float* codes = out + (size_t)M_TOTAL * C_;               // M*G
    float* probs = codes + (size_t)M_TOTAL * G_;             // M*N1

    float* logits_ptr = nullptr;
    cudaGetSymbolAddress((void**)&logits_ptr, g_logits);

    // GEMM1: logits = x @ W + b   (M x 768) @ (768 x 320)
    {
        dim3 grid(N1 / BN, M_TOTAL / BM);   // (5, 384)
        gemm_tf32<true><<<grid, 256>>>(x, W, bias, logits_ptr, K1, N1);
    }
    // Softmax + argmax (+rescue) + probs
    {
        softmax_argmax_kernel<<<(M_TOTAL * G_) / 8, 256>>>(gumbel, x, W, bias, probs, codes);
    }
    // GEMM2: quantized = probs @ codebook   (M x 320) @ (320 x 768)
    {
        dim3 grid(N2 / BN, M_TOTAL / BM);   // (12, 384)
        gemm_tf32<false><<<grid, 256>>>(probs, cb, nullptr, quant, K2, N2);
    }
}